// round 2
// baseline (speedup 1.0000x reference)
#include <cuda_runtime.h>
#include <cstdint>
#include <math.h>

#define Bn 2
#define Ln 2048
#define Dn 1024
#define Hn 16
#define DKn 64
#define BHn (Bn*Hn)      // 32
#define Mn (Bn*Ln)       // 4096

// Scratch (device globals — no allocation allowed)
__device__ float g_k[(size_t)BHn*Ln*DKn];
__device__ float g_v[(size_t)BHn*Ln*DKn];
__device__ float g_q[(size_t)BHn*Ln*DKn];
__device__ float g_o[(size_t)BHn*Ln*DKn];
__device__ float g_rm[(size_t)BHn*Ln];
__device__ float g_rs[(size_t)BHn*Ln];
// Fallback scores buffer in case the harness output holds only `normed`
__device__ float g_sc[(size_t)BHn*Ln*Ln];

// ---------------------------------------------------------------------------
// Projection GEMM: out[b,h,l,dk] = sum_d X[b,l,d] * W[d, h*DK+dk]
// M=4096, N=1024, K=1024. 128x128 tile, BK=8, 8x8 per thread, 256 threads.
// ---------------------------------------------------------------------------
__global__ __launch_bounds__(256) void proj_kernel(const float* __restrict__ X,
                                                   const float* __restrict__ W,
                                                   int which) {
    float* out = (which == 0) ? g_k : ((which == 1) ? g_v : g_q);
    __shared__ float As[8][132];
    __shared__ float Bs[8][132];
    const int bm = blockIdx.y * 128;
    const int bn = blockIdx.x * 128;
    const int tid = threadIdx.x;
    const int tx = tid & 15, ty = tid >> 4;

    float acc[8][8];
    #pragma unroll
    for (int i = 0; i < 8; i++)
        #pragma unroll
        for (int j = 0; j < 8; j++) acc[i][j] = 0.f;

    const int am = tid >> 1;
    const int ak = (tid & 1) * 4;
    const int bk = tid >> 5;
    const int bn4 = (tid & 31) * 4;

    for (int k0 = 0; k0 < Dn; k0 += 8) {
        float4 a = *(const float4*)&X[(size_t)(bm + am) * Dn + k0 + ak];
        As[ak+0][am] = a.x; As[ak+1][am] = a.y;
        As[ak+2][am] = a.z; As[ak+3][am] = a.w;
        float4 b = *(const float4*)&W[(size_t)(k0 + bk) * Dn + bn + bn4];
        *(float4*)&Bs[bk][bn4] = b;
        __syncthreads();
        #pragma unroll
        for (int kk = 0; kk < 8; kk++) {
            float ra[8], rb[8];
            *(float4*)&ra[0] = *(const float4*)&As[kk][ty*8];
            *(float4*)&ra[4] = *(const float4*)&As[kk][ty*8+4];
            *(float4*)&rb[0] = *(const float4*)&Bs[kk][tx*8];
            *(float4*)&rb[4] = *(const float4*)&Bs[kk][tx*8+4];
            #pragma unroll
            for (int i = 0; i < 8; i++)
                #pragma unroll
                for (int j = 0; j < 8; j++)
                    acc[i][j] = fmaf(ra[i], rb[j], acc[i][j]);
        }
        __syncthreads();
    }
    const int n0 = bn + tx*8;
    const int h = n0 >> 6;       // 8 | 64, so the 8 columns stay in one head
    const int dk = n0 & 63;
    #pragma unroll
    for (int i = 0; i < 8; i++) {
        int m = bm + ty*8 + i;
        int bb = m >> 11, l = m & (Ln-1);
        float* po = &out[(((size_t)(bb*Hn + h))*Ln + l)*DKn + dk];
        *(float4*)&po[0] = make_float4(acc[i][0],acc[i][1],acc[i][2],acc[i][3]);
        *(float4*)&po[4] = make_float4(acc[i][4],acc[i][5],acc[i][6],acc[i][7]);
    }
}

// ---------------------------------------------------------------------------
// Scores: sc[bh,q,j] = (q.k)/8, masked (mask marshalled as int32);
// also per-row online (max, sumexp).
// Block: 64 q-rows x all 2048 j (chunks of 64). Thread: 4q x 4j.
// ---------------------------------------------------------------------------
__global__ __launch_bounds__(256) void scores_kernel(const int* __restrict__ mask,
                                                     float* __restrict__ sc) {
    const int bh = blockIdx.y;
    const int q0 = blockIdx.x * 64;
    const int b = bh >> 4;               // bh / H
    const int tid = threadIdx.x;
    const int tx = tid & 15, ty = tid >> 4;

    __shared__ float Qs[64][68];   // Qs[d][q]
    __shared__ float Ks[64][68];   // Ks[d][j]

    for (int e = tid; e < 64*64; e += 256) {
        int q = e >> 6, d = e & 63;
        Qs[d][q] = g_q[(((size_t)bh)*Ln + q0 + q)*DKn + d];
    }

    float m[4], l[4];
    #pragma unroll
    for (int i = 0; i < 4; i++) { m[i] = -1e30f; l[i] = 0.f; }

    for (int j0 = 0; j0 < Ln; j0 += 64) {
        __syncthreads();
        for (int e = tid; e < 64*64; e += 256) {
            int j = e >> 6, d = e & 63;
            Ks[d][j] = g_k[(((size_t)bh)*Ln + j0 + j)*DKn + d];
        }
        __syncthreads();

        float acc[4][4];
        #pragma unroll
        for (int i = 0; i < 4; i++)
            #pragma unroll
            for (int j = 0; j < 4; j++) acc[i][j] = 0.f;

        #pragma unroll 8
        for (int kk = 0; kk < 64; kk++) {
            float qa[4], ka[4];
            *(float4*)qa = *(const float4*)&Qs[kk][ty*4];
            *(float4*)ka = *(const float4*)&Ks[kk][tx*4];
            #pragma unroll
            for (int i = 0; i < 4; i++)
                #pragma unroll
                for (int j = 0; j < 4; j++)
                    acc[i][j] = fmaf(qa[i], ka[j], acc[i][j]);
        }

        #pragma unroll
        for (int i = 0; i < 4; i++) {
            int q = q0 + ty*4 + i;
            size_t mbase = ((size_t)b*Ln + q)*Ln + j0 + tx*4;
            int4 mv = *(const int4*)(mask + mbase);
            float v[4];
            v[0] = mv.x ? -1e9f : acc[i][0]*0.125f;
            v[1] = mv.y ? -1e9f : acc[i][1]*0.125f;
            v[2] = mv.z ? -1e9f : acc[i][2]*0.125f;
            v[3] = mv.w ? -1e9f : acc[i][3]*0.125f;
            float lm = fmaxf(fmaxf(v[0],v[1]), fmaxf(v[2],v[3]));
            float nm = fmaxf(m[i], lm);
            float add = __expf(v[0]-nm) + __expf(v[1]-nm) +
                        __expf(v[2]-nm) + __expf(v[3]-nm);
            l[i] = l[i]*__expf(m[i]-nm) + add;
            m[i] = nm;
            size_t sbase = ((size_t)bh*Ln + q)*Ln + j0 + tx*4;
            *(float4*)(sc + sbase) = make_float4(v[0],v[1],v[2],v[3]);
        }
    }

    // cross-thread (m,l) merge: 16 tx lanes share each q-row (within-warp groups)
    #pragma unroll
    for (int i = 0; i < 4; i++) {
        float m_ = m[i], l_ = l[i];
        #pragma unroll
        for (int off = 8; off; off >>= 1) {
            float mo = __shfl_xor_sync(0xffffffffu, m_, off);
            float lo = __shfl_xor_sync(0xffffffffu, l_, off);
            float nm = fmaxf(m_, mo);
            l_ = l_*__expf(m_-nm) + lo*__expf(mo-nm);
            m_ = nm;
        }
        if (tx == 0) {
            int q = q0 + ty*4 + i;
            g_rm[(size_t)bh*Ln + q] = m_;
            g_rs[(size_t)bh*Ln + q] = l_;
        }
    }
}

// ---------------------------------------------------------------------------
// PV: normalize scores in place (final attn output) and accumulate attn @ V.
// Block: 128 q x 64 dk, j chunks of 32. Thread: 8q x 4dk.
// ---------------------------------------------------------------------------
__global__ __launch_bounds__(256) void pv_kernel(float* __restrict__ sc) {
    const int bh = blockIdx.y;
    const int q0 = blockIdx.x * 128;
    const int tid = threadIdx.x;
    const int tx = tid & 15, ty = tid >> 4;

    __shared__ float Ps[32][132];  // Ps[j][q]
    __shared__ float Vs[32][64];   // Vs[j][dk]
    __shared__ float rmS[128];
    __shared__ float riS[128];

    if (tid < 128) {
        rmS[tid] = g_rm[(size_t)bh*Ln + q0 + tid];
        riS[tid] = 1.0f / g_rs[(size_t)bh*Ln + q0 + tid];
    }

    float acc[8][4];
    #pragma unroll
    for (int i = 0; i < 8; i++)
        #pragma unroll
        for (int c = 0; c < 4; c++) acc[i][c] = 0.f;

    for (int j0 = 0; j0 < Ln; j0 += 32) {
        __syncthreads();
        for (int e = tid; e < 128*32; e += 256) {
            int q = e >> 5, j = e & 31;
            size_t gi = (((size_t)bh)*Ln + q0 + q)*Ln + j0 + j;
            float s = sc[gi];
            float p = __expf(s - rmS[q]) * riS[q];
            sc[gi] = p;         // final attn output (in place)
            Ps[j][q] = p;
        }
        for (int e = tid; e < 32*64; e += 256) {
            int j = e >> 6, d = e & 63;
            Vs[j][d] = g_v[(((size_t)bh)*Ln + j0 + j)*DKn + d];
        }
        __syncthreads();
        #pragma unroll 8
        for (int jj = 0; jj < 32; jj++) {
            float pv[8], vv[4];
            *(float4*)&pv[0] = *(const float4*)&Ps[jj][ty*8];
            *(float4*)&pv[4] = *(const float4*)&Ps[jj][ty*8+4];
            *(float4*)&vv[0] = *(const float4*)&Vs[jj][tx*4];
            #pragma unroll
            for (int i = 0; i < 8; i++)
                #pragma unroll
                for (int c = 0; c < 4; c++)
                    acc[i][c] = fmaf(pv[i], vv[c], acc[i][c]);
        }
    }

    #pragma unroll
    for (int i = 0; i < 8; i++) {
        int q = q0 + ty*8 + i;
        float* po = &g_o[(((size_t)bh)*Ln + q)*DKn + tx*4];
        *(float4*)po = make_float4(acc[i][0],acc[i][1],acc[i][2],acc[i][3]);
    }
}

// ---------------------------------------------------------------------------
// Residual + LayerNorm: normed[b,l,d] over D=1024, one block per (b,l).
// ---------------------------------------------------------------------------
__global__ __launch_bounds__(256) void ln_kernel(const float* __restrict__ query,
                                                 const float* __restrict__ gamma,
                                                 const float* __restrict__ beta,
                                                 float* __restrict__ out) {
    const int row = blockIdx.x;          // b*L + l
    const int b = row >> 11, l = row & (Ln-1);
    const int tid = threadIdx.x;
    float vals[4];
    float s = 0.f, ss = 0.f;
    #pragma unroll
    for (int it = 0; it < 4; it++) {
        int d = tid + it*256;
        int h = d >> 6, dk = d & 63;
        float o = g_o[(((size_t)(b*Hn + h))*Ln + l)*DKn + dk];
        float r = o + query[(size_t)row*Dn + d];
        vals[it] = r;
        s += r; ss += r*r;
    }
    __shared__ float sm[8], sq[8], stat[2];
    #pragma unroll
    for (int off = 16; off; off >>= 1) {
        s  += __shfl_xor_sync(0xffffffffu, s, off);
        ss += __shfl_xor_sync(0xffffffffu, ss, off);
    }
    int warp = tid >> 5, lane = tid & 31;
    if (lane == 0) { sm[warp] = s; sq[warp] = ss; }
    __syncthreads();
    if (tid == 0) {
        float S = 0.f, SS = 0.f;
        #pragma unroll
        for (int w = 0; w < 8; w++) { S += sm[w]; SS += sq[w]; }
        float mu = S * (1.0f/Dn);
        float var = SS * (1.0f/Dn) - mu*mu;
        stat[0] = mu;
        stat[1] = rsqrtf(var + 1e-6f);
    }
    __syncthreads();
    float mu = stat[0], rstd = stat[1];
    #pragma unroll
    for (int it = 0; it < 4; it++) {
        int d = tid + it*256;
        out[(size_t)row*Dn + d] = (vals[it] - mu) * rstd * gamma[d] + beta[d];
    }
}

// ---------------------------------------------------------------------------
extern "C" void kernel_launch(void* const* d_in, const int* in_sizes, int n_in,
                              void* d_out, int out_size) {
    const float* key   = (const float*)d_in[0];
    const float* value = (const float*)d_in[1];
    const float* query = (const float*)d_in[2];
    const int*   mask  = (const int*)d_in[3];
    const float* Wk = (const float*)d_in[4];
    const float* Wv = (const float*)d_in[5];
    const float* Wq = (const float*)d_in[6];
    const float* lng = (const float*)d_in[7];
    const float* lnb = (const float*)d_in[8];

    float* normed = (float*)d_out;                       // [B, L, D]
    // attn [B*H, L, L] follows normed in d_out if the harness checks it;
    // otherwise use the device-global scratch.
    float* attn;
    if ((size_t)out_size > (size_t)Bn*Ln*Dn) {
        attn = normed + (size_t)Bn*Ln*Dn;
    } else {
        cudaGetSymbolAddress((void**)&attn, g_sc);
    }

    dim3 gp(Dn/128, Mn/128);     // (8, 32)
    proj_kernel<<<gp, 256>>>(key,   Wk, 0);
    proj_kernel<<<gp, 256>>>(value, Wv, 1);
    proj_kernel<<<gp, 256>>>(query, Wq, 2);

    dim3 gs(Ln/64, BHn);         // (32, 32)
    scores_kernel<<<gs, 256>>>(mask, attn);

    dim3 gv(Ln/128, BHn);        // (16, 32)
    pv_kernel<<<gv, 256>>>(attn);

    ln_kernel<<<Mn, 256>>>(query, lng, lnb, normed);
}